// round 10
// baseline (speedup 1.0000x reference)
#include <cuda_runtime.h>
#include <cuda_fp16.h>
#include <cstdint>

#define MTOK   8192
#define DMODEL 2048
#define DFF    8192
#define NGX    (DMODEL/64)
#define NGH    (DFF/64)

// ---------------- scratch (device globals; no allocations allowed) ----------
__device__ __half g_w1h[DFF*DMODEL];
__device__ __half g_w2h[DFF*DMODEL];
__device__ __half g_w3h[DMODEL*DFF];
__device__ __half g_xqh[MTOK*DMODEL];          // quantized x as exact fp16 integers
__device__ float  g_sx [MTOK*NGX];
__device__ __half g_hqh[(size_t)MTOK*DFF];     // quantized h as exact fp16 integers
__device__ float  g_sh [MTOK*NGH];
__device__ float  g_partial[3][2048];
__device__ float  g_wscale[3];

// ---------------- small helpers --------------------------------------------
__device__ __forceinline__ void ldsm4(uint32_t r[4], uint32_t addr){
  asm volatile("ldmatrix.sync.aligned.m8n8.x4.shared.b16 {%0,%1,%2,%3},[%4];"
               : "=r"(r[0]),"=r"(r[1]),"=r"(r[2]),"=r"(r[3]) : "r"(addr));
}
__device__ __forceinline__ void ldsm2(uint32_t r[2], uint32_t addr){
  asm volatile("ldmatrix.sync.aligned.m8n8.x2.shared.b16 {%0,%1},[%2];"
               : "=r"(r[0]),"=r"(r[1]) : "r"(addr));
}
__device__ __forceinline__ void hmma(float d[4], const uint32_t a[4], const uint32_t b[2]){
  asm volatile("mma.sync.aligned.m16n8k16.row.col.f32.f16.f16.f32 "
               "{%0,%1,%2,%3},{%4,%5,%6,%7},{%8,%9},{%0,%1,%2,%3};"
               : "+f"(d[0]),"+f"(d[1]),"+f"(d[2]),"+f"(d[3])
               : "r"(a[0]),"r"(a[1]),"r"(a[2]),"r"(a[3]),"r"(b[0]),"r"(b[1]));
}
__device__ __forceinline__ void cpa16(uint32_t d, const void* s){
  asm volatile("cp.async.cg.shared.global [%0],[%1],16;" :: "r"(d),"l"(s));
}
__device__ __forceinline__ void cpa4(uint32_t d, const void* s){
  asm volatile("cp.async.ca.shared.global [%0],[%1],4;" :: "r"(d),"l"(s));
}

// ---------------- prep: sign(w)->fp16 ±1 + per-block |w| partial sums -------
__global__ void prep_all(const float4* __restrict__ w1, const float4* __restrict__ w2,
                         const float4* __restrict__ w3, __half2* __restrict__ o1,
                         __half2* __restrict__ o2, __half2* __restrict__ o3, int n4){
  const int idx = blockIdx.y;
  const float4* __restrict__ w = (idx==0)?w1:((idx==1)?w2:w3);
  __half2* __restrict__ o = (idx==0)?o1:((idx==1)?o2:o3);
  float acc=0.f;
  for (int i=blockIdx.x*blockDim.x+threadIdx.x; i<n4; i+=gridDim.x*blockDim.x){
    float4 v=w[i];
    acc += fabsf(v.x)+fabsf(v.y)+fabsf(v.z)+fabsf(v.w);
    o[2*i  ] = __floats2half2_rn((float)((v.x>0.f)-(v.x<0.f)), (float)((v.y>0.f)-(v.y<0.f)));
    o[2*i+1] = __floats2half2_rn((float)((v.z>0.f)-(v.z<0.f)), (float)((v.w>0.f)-(v.w<0.f)));
  }
  __shared__ float sm[256];
  sm[threadIdx.x]=acc; __syncthreads();
  for (int t=128;t>0;t>>=1){ if(threadIdx.x<t) sm[threadIdx.x]+=sm[threadIdx.x+t]; __syncthreads(); }
  if (threadIdx.x==0) g_partial[idx][blockIdx.x]=sm[0];
}
__global__ void absmean_final3(float inv_n){
  __shared__ float sm[256];
  int idx=blockIdx.x; float s=0.f;
  for (int i=threadIdx.x;i<2048;i+=256) s+=g_partial[idx][i];
  sm[threadIdx.x]=s; __syncthreads();
  for (int t=128;t>0;t>>=1){ if(threadIdx.x<t) sm[threadIdx.x]+=sm[threadIdx.x+t]; __syncthreads(); }
  if (threadIdx.x==0) g_wscale[idx]=sm[0]*inv_n;
}

// ---------------- per-64-group quant: store integer q as exact fp16 ----------
__global__ void quant_kernel(const float2* __restrict__ src, __half2* __restrict__ q,
                             float* __restrict__ sc, int ngroups){
  int w=(blockIdx.x*blockDim.x+threadIdx.x)>>5, lane=threadIdx.x&31, nw=(gridDim.x*blockDim.x)>>5;
  for (int g=w; g<ngroups; g+=nw){
    float2 v = src[g*32+lane];
    float m = fmaxf(fabsf(v.x),fabsf(v.y));
#pragma unroll
    for (int o=16;o;o>>=1) m=fmaxf(m,__shfl_xor_sync(0xffffffffu,m,o));
    float s=fmaxf(m,1e-5f), inv=127.0f/s;
    float q0=(float)__float2int_rn(v.x*inv);
    float q1=(float)__float2int_rn(v.y*inv);
    q[g*32+lane]=__floats2half2_rn(q0,q1);
    if (lane==0) sc[g]=s*(1.0f/127.0f);
  }
}

// ---------------- grouped fp16 GEMM (exact-integer), 512 thr / 16 warps ------
// CTA tile 128x128, warp grid 4x4, warp tile 32x32 (MT=2 m16, NT=4 n8), K-chunk 64.
// A = q (fp16-exact ints), B = ±1 fp16; d accumulated fp32 (exact) then folded by s/127.
// MODE 0: dual-B (w1,w2); epilogue SwiGLU + fused 64-col-group quant -> g_hqh,g_sh
// MODE 1: single-B (w3); epilogue scale -> C
#define ATILE 16384    // 128 rows x 128 B (64 halves)

template<int NB, int KTOT>
__device__ __forceinline__ void load_stage_d(uint32_t st, const __half* A, const float* sA,
    const __half* B1, const __half* B2, int m0, int n0, int g, int tid)
{
#pragma unroll
  for (int t=0;t<2;t++){
    int i = tid + t*512, r = i>>3, c = i&7;
    cpa16(st + r*128 + ((c ^ (r&7))<<4), A + (size_t)(m0+r)*KTOT + g*64 + c*8);
  }
#pragma unroll
  for (int b=0;b<NB;b++){
    const __half* Bp = b ? B2 : B1;
#pragma unroll
    for (int t=0;t<2;t++){
      int i = tid + t*512, r = i>>3, c = i&7;
      cpa16(st + ATILE*(1+b) + r*128 + ((c ^ (r&7))<<4),
            Bp + (size_t)(n0+r)*KTOT + g*64 + c*8);
    }
  }
  if (tid < 128) cpa4(st + ATILE*(1+NB) + tid*4, sA + (size_t)(m0+tid)*(KTOT/64) + g);
  asm volatile("cp.async.commit_group;");
}

template<int MODE, int KTOT>
__global__ void __launch_bounds__(512,1) gemm_f16(
    const __half* __restrict__ A, const float* __restrict__ sA,
    const __half* __restrict__ B1, const __half* __restrict__ B2,
    float* __restrict__ C)
{
  constexpr int NB    = (MODE==0) ? 2 : 1;
  constexpr int NG    = KTOT/64;
  constexpr int STAGE = ATILE*(1+NB) + 512;
  extern __shared__ char smem[];
  const uint32_t sb = (uint32_t)__cvta_generic_to_shared(smem);
  const int tid = threadIdx.x, lane = tid&31, wid = tid>>5;
  const int m0 = blockIdx.y*128, n0 = blockIdx.x*128;
  const int wm = (wid>>2)*32, wn = (wid&3)*32;

  // ldmatrix lane address components
  const int arow = lane&15;          // A row within m16
  const int acs  = lane>>4;          // A 16B-chunk select (k half)
  const int brow = lane&7;           // B row within n8
  const int bcs  = (lane>>3)&1;      // B 16B-chunk select

  float f1[2][4][4]; float f2[2][4][4];
#pragma unroll
  for (int i=0;i<2;i++)
#pragma unroll
    for (int j=0;j<4;j++)
#pragma unroll
      for (int k=0;k<4;k++){ f1[i][j][k]=0.f; if (MODE==0) f2[i][j][k]=0.f; }

  load_stage_d<NB,KTOT>(sb, A, sA, B1, B2, m0, n0, 0, tid);

#pragma unroll 1
  for (int g=0; g<NG; ++g){
    const int s = g&1;
    if (g+1 < NG){
      load_stage_d<NB,KTOT>(sb + (s^1)*STAGE, A, sA, B1, B2, m0, n0, g+1, tid);
      asm volatile("cp.async.wait_group 1;");
    } else {
      asm volatile("cp.async.wait_group 0;");
    }
    __syncthreads();

    const uint32_t st = sb + s*STAGE;
    const float* sf = (const float*)(smem + s*STAGE + ATILE*(1+NB));
    float sc[2][2];
#pragma unroll
    for (int mt=0;mt<2;mt++){
      sc[mt][0] = sf[wm + mt*16 + (lane>>2)];
      sc[mt][1] = sf[wm + mt*16 + (lane>>2) + 8];
    }

    // ---- B1 ----
    {
      float dt[2][4][4];
#pragma unroll
      for (int i=0;i<2;i++)
#pragma unroll
        for (int j=0;j<4;j++)
#pragma unroll
          for (int k=0;k<4;k++) dt[i][j][k]=0.f;
#pragma unroll
      for (int ks=0;ks<4;ks++){
        uint32_t a[2][4], b[4][2];
#pragma unroll
        for (int mt=0;mt<2;mt++){
          int row = wm + mt*16 + arow, c = ks*2 + acs;
          ldsm4(a[mt], st + row*128 + ((c ^ (row&7))<<4));
        }
#pragma unroll
        for (int nt=0;nt<4;nt++){
          int row = wn + nt*8 + brow, c = ks*2 + bcs;
          ldsm2(b[nt], st + ATILE + row*128 + ((c ^ (row&7))<<4));
        }
#pragma unroll
        for (int mt=0;mt<2;mt++)
#pragma unroll
          for (int nt=0;nt<4;nt++) hmma(dt[mt][nt], a[mt], b[nt]);
      }
#pragma unroll
      for (int mt=0;mt<2;mt++)
#pragma unroll
        for (int nt=0;nt<4;nt++){
          f1[mt][nt][0] += sc[mt][0]*dt[mt][nt][0];
          f1[mt][nt][1] += sc[mt][0]*dt[mt][nt][1];
          f1[mt][nt][2] += sc[mt][1]*dt[mt][nt][2];
          f1[mt][nt][3] += sc[mt][1]*dt[mt][nt][3];
        }
    }
    // ---- B2 (MODE 0) ----
    if (MODE==0){
      float dt[2][4][4];
#pragma unroll
      for (int i=0;i<2;i++)
#pragma unroll
        for (int j=0;j<4;j++)
#pragma unroll
          for (int k=0;k<4;k++) dt[i][j][k]=0.f;
#pragma unroll
      for (int ks=0;ks<4;ks++){
        uint32_t a[2][4], b[4][2];
#pragma unroll
        for (int mt=0;mt<2;mt++){
          int row = wm + mt*16 + arow, c = ks*2 + acs;
          ldsm4(a[mt], st + row*128 + ((c ^ (row&7))<<4));
        }
#pragma unroll
        for (int nt=0;nt<4;nt++){
          int row = wn + nt*8 + brow, c = ks*2 + bcs;
          ldsm2(b[nt], st + 2*ATILE + row*128 + ((c ^ (row&7))<<4));
        }
#pragma unroll
        for (int mt=0;mt<2;mt++)
#pragma unroll
          for (int nt=0;nt<4;nt++) hmma(dt[mt][nt], a[mt], b[nt]);
      }
#pragma unroll
      for (int mt=0;mt<2;mt++)
#pragma unroll
        for (int nt=0;nt<4;nt++){
          f2[mt][nt][0] += sc[mt][0]*dt[mt][nt][0];
          f2[mt][nt][1] += sc[mt][0]*dt[mt][nt][1];
          f2[mt][nt][2] += sc[mt][1]*dt[mt][nt][2];
          f2[mt][nt][3] += sc[mt][1]*dt[mt][nt][3];
        }
    }
    __syncthreads();
  }

  // ---------------- epilogue ----------------
  if (MODE==0){
    // SwiGLU, then fused per-64-col quant. Quant group = warp pair (wn, wn^32).
    float* smax = (float*)smem;                  // [grp(2)][half(2)][row(128)]
    const float c1=g_wscale[0], c2=g_wscale[1];
    const int grp = wn>>6, halfw=(wn>>5)&1;
    float rmax[2][2];
#pragma unroll
    for (int mt=0;mt<2;mt++)
#pragma unroll
      for (int hr=0;hr<2;hr++){
        float m=0.f;
#pragma unroll
        for (int nt=0;nt<4;nt++)
#pragma unroll
          for (int e=0;e<2;e++){
            float u=c1*f1[mt][nt][hr*2+e];
            float v=c2*f2[mt][nt][hr*2+e];
            float h=(u/(1.f+expf(-u)))*v;
            f1[mt][nt][hr*2+e]=h;
            m=fmaxf(m,fabsf(h));
          }
        m=fmaxf(m,__shfl_xor_sync(0xffffffffu,m,1));
        m=fmaxf(m,__shfl_xor_sync(0xffffffffu,m,2));
        rmax[mt][hr]=m;
      }
    if ((lane&3)==0){
#pragma unroll
      for (int mt=0;mt<2;mt++)
#pragma unroll
        for (int hr=0;hr<2;hr++){
          int rr=wm+mt*16+(lane>>2)+hr*8;
          smax[(grp*2+halfw)*128+rr]=rmax[mt][hr];
        }
    }
    __syncthreads();
#pragma unroll
    for (int mt=0;mt<2;mt++)
#pragma unroll
      for (int hr=0;hr<2;hr++){
        int rr=wm+mt*16+(lane>>2)+hr*8;
        int row=m0+rr;
        float m=fmaxf(rmax[mt][hr], smax[(grp*2+(halfw^1))*128+rr]);
        float s=fmaxf(m,1e-5f), inv=127.0f/s;
#pragma unroll
        for (int nt=0;nt<4;nt++){
          float q0=(float)__float2int_rn(f1[mt][nt][hr*2+0]*inv);
          float q1=(float)__float2int_rn(f1[mt][nt][hr*2+1]*inv);
          *(__half2*)&g_hqh[(size_t)row*DFF + n0+wn+nt*8+(lane&3)*2] = __floats2half2_rn(q0,q1);
        }
        if (halfw==0 && (lane&3)==0)
          g_sh[(size_t)row*NGH + (n0>>6)+grp]=s*(1.0f/127.0f);
      }
  } else {
    const float c3=g_wscale[2];
#pragma unroll
    for (int mt=0;mt<2;mt++)
#pragma unroll
      for (int nt=0;nt<4;nt++)
#pragma unroll
        for (int hr=0;hr<2;hr++){
          int row  = m0 + wm + mt*16 + (lane>>2) + hr*8;
          int cidx = n0 + wn + nt*8 + (lane&3)*2;
          *(float2*)&C[(size_t)row*DMODEL + cidx] =
              make_float2(c3*f1[mt][nt][hr*2+0], c3*f1[mt][nt][hr*2+1]);
        }
  }
}

// ---------------- host launcher ---------------------------------------------
extern "C" void kernel_launch(void* const* d_in, const int* in_sizes, int n_in,
                              void* d_out, int out_size)
{
  const float* x  = (const float*)d_in[0];
  const float* w1 = (const float*)d_in[1];
  const float* w2 = (const float*)d_in[2];
  const float* w3 = (const float*)d_in[3];

  void *w1h,*w2h,*w3h,*xq,*sx,*hq,*sh;
  cudaGetSymbolAddress(&w1h,g_w1h); cudaGetSymbolAddress(&w2h,g_w2h);
  cudaGetSymbolAddress(&w3h,g_w3h); cudaGetSymbolAddress(&xq ,g_xqh);
  cudaGetSymbolAddress(&sx ,g_sx ); cudaGetSymbolAddress(&hq ,g_hqh);
  cudaGetSymbolAddress(&sh ,g_sh );

  const int NW = DFF*DMODEL;       // 16.7M, same count for all three weights
  constexpr int SM0 = 2*(ATILE*3 + 512);   // 99328 B
  constexpr int SM1 = 2*(ATILE*2 + 512);   // 66560 B
  cudaFuncSetAttribute(gemm_f16<0,DMODEL>, cudaFuncAttributeMaxDynamicSharedMemorySize, SM0);
  cudaFuncSetAttribute(gemm_f16<1,DFF>,    cudaFuncAttributeMaxDynamicSharedMemorySize, SM1);

  // L1: fused sign-pack + abs-sum partials for all three weights
  prep_all<<<dim3(2048,3),256>>>((const float4*)w1,(const float4*)w2,(const float4*)w3,
                                 (__half2*)w1h,(__half2*)w2h,(__half2*)w3h, NW/4);
  // L2: quantize x (store exact integer q as fp16)
  quant_kernel<<<2048,256>>>((const float2*)x, (__half2*)xq, (float*)sx, MTOK*NGX);
  // L3: finalize weight scales
  absmean_final3<<<3,256>>>(1.0f/(float)NW);
  // L4: fused GEMM1+2 + SwiGLU + h-quant -> g_hqh/g_sh
  gemm_f16<0,DMODEL><<<dim3(DFF/128, MTOK/128), 512, SM0>>>(
      (const __half*)xq, (const float*)sx,
      (const __half*)w1h, (const __half*)w2h, nullptr);
  // L5: GEMM3 -> out
  gemm_f16<1,DFF><<<dim3(DMODEL/128, MTOK/128), 512, SM1>>>(
      (const __half*)hq, (const float*)sh,
      (const __half*)w3h, nullptr, (float*)d_out);
}

// round 13
// speedup vs baseline: 2.0199x; 2.0199x over previous
#include <cuda_runtime.h>
#include <cuda_fp16.h>
#include <cstdint>

#define MTOK   8192
#define DMODEL 2048
#define DFF    8192
#define NGX    (DMODEL/64)
#define NGH    (DFF/64)
#define NWORDS ((DFF*DMODEL)/32)   // 524288 packed words per weight matrix

// ---------------- scratch (device globals; no allocations allowed) ----------
__device__ uint32_t g_w1b[NWORDS];
__device__ uint32_t g_w2b[NWORDS];
__device__ uint32_t g_w3b[NWORDS];
__device__ __half   g_xqh[MTOK*DMODEL];        // quantized x as exact fp16 integers
__device__ float    g_sx [MTOK*NGX];
__device__ __half   g_hqh[(size_t)MTOK*DFF];   // quantized h as exact fp16 integers
__device__ float    g_sh [MTOK*NGH];
__device__ float    g_partial[3][2048];
__device__ float    g_wscale[3];

// ---------------- small helpers --------------------------------------------
__device__ __forceinline__ void ldsm4(uint32_t r[4], uint32_t addr){
  asm volatile("ldmatrix.sync.aligned.m8n8.x4.shared.b16 {%0,%1,%2,%3},[%4];"
               : "=r"(r[0]),"=r"(r[1]),"=r"(r[2]),"=r"(r[3]) : "r"(addr));
}
__device__ __forceinline__ void hmma(float d[4], const uint32_t a[4], const uint32_t b[2]){
  asm volatile("mma.sync.aligned.m16n8k16.row.col.f32.f16.f16.f32 "
               "{%0,%1,%2,%3},{%4,%5,%6,%7},{%8,%9},{%0,%1,%2,%3};"
               : "+f"(d[0]),"+f"(d[1]),"+f"(d[2]),"+f"(d[3])
               : "r"(a[0]),"r"(a[1]),"r"(a[2]),"r"(a[3]),"r"(b[0]),"r"(b[1]));
}
__device__ __forceinline__ void cpa16(uint32_t d, const void* s){
  asm volatile("cp.async.cg.shared.global [%0],[%1],16;" :: "r"(d),"l"(s));
}
__device__ __forceinline__ void cpa4(uint32_t d, const void* s){
  asm volatile("cp.async.ca.shared.global [%0],[%1],4;" :: "r"(d),"l"(s));
}
__device__ __forceinline__ uint32_t lds32(uint32_t addr){
  uint32_t v; asm volatile("ld.shared.b32 %0,[%1];" : "=r"(v) : "r"(addr)); return v;
}

// ---------------- prep: pack sign bits + per-block |w| partial sums ----------
// Word layout: widx = nt*(K/64)*16 + kg*16 + j*4 + t  (tile ktile=kg*4+t, word j)
// Word j of tile (nt,ktile): nibble i (lane l=8j+i): n = nt*8+2j+(i>>2), c=i&3,
// bits: k=ktile*16 + {2c, 2c+1, 2c+8, 2c+9}; bit set = weight negative.
__global__ void prep_pack(const float* __restrict__ w1, const float* __restrict__ w2,
                          const float* __restrict__ w3, uint32_t* __restrict__ b1,
                          uint32_t* __restrict__ b2, uint32_t* __restrict__ b3){
  const int idx = blockIdx.y;
  const float* __restrict__ w = (idx==0)?w1:((idx==1)?w2:w3);
  uint32_t* __restrict__ bits = (idx==0)?b1:((idx==1)?b2:b3);
  const int Kdim  = (idx==2)? DFF : DMODEL;
  const int kgcnt = Kdim/64;

  int widx = blockIdx.x*blockDim.x + threadIdx.x;   // grid exactly NWORDS threads
  int t = widx&3, j=(widx>>2)&3;
  int rest = widx>>4;
  int kg = rest & (kgcnt-1);
  int nt = rest / kgcnt;
  int ktile = kg*4 + t;
  int n0 = nt*8 + 2*j;

  const float4* r0 = (const float4*)(w + (size_t)n0*Kdim + ktile*16);
  const float4* r1 = (const float4*)(w + (size_t)(n0+1)*Kdim + ktile*16);
  float v[2][16];
#pragma unroll
  for (int q=0;q<4;q++){ float4 a=r0[q]; v[0][4*q]=a.x; v[0][4*q+1]=a.y; v[0][4*q+2]=a.z; v[0][4*q+3]=a.w; }
#pragma unroll
  for (int q=0;q<4;q++){ float4 a=r1[q]; v[1][4*q]=a.x; v[1][4*q+1]=a.y; v[1][4*q+2]=a.z; v[1][4*q+3]=a.w; }

  float acc=0.f;
#pragma unroll
  for (int r=0;r<2;r++)
#pragma unroll
    for (int q=0;q<16;q++) acc += fabsf(v[r][q]);

  uint32_t word=0;
#pragma unroll
  for (int i=0;i<8;i++){
    const float* rv = v[i>>2];
    int c = i&3;
    uint32_t nib = (uint32_t)(rv[2*c]<0.f) | ((uint32_t)(rv[2*c+1]<0.f)<<1)
                 | ((uint32_t)(rv[2*c+8]<0.f)<<2) | ((uint32_t)(rv[2*c+9]<0.f)<<3);
    word |= nib << (4*i);
  }
  bits[widx]=word;

  __shared__ float sm[256];
  sm[threadIdx.x]=acc; __syncthreads();
  for (int s=128;s>0;s>>=1){ if(threadIdx.x<s) sm[threadIdx.x]+=sm[threadIdx.x+s]; __syncthreads(); }
  if (threadIdx.x==0) g_partial[idx][blockIdx.x]=sm[0];
}
__global__ void absmean_final3(float inv_n){
  __shared__ float sm[256];
  int idx=blockIdx.x; float s=0.f;
  for (int i=threadIdx.x;i<2048;i+=256) s+=g_partial[idx][i];
  sm[threadIdx.x]=s; __syncthreads();
  for (int t=128;t>0;t>>=1){ if(threadIdx.x<t) sm[threadIdx.x]+=sm[threadIdx.x+t]; __syncthreads(); }
  if (threadIdx.x==0) g_wscale[idx]=sm[0]*inv_n;
}

// ---------------- per-64-group quant: store integer q as exact fp16 ----------
__global__ void quant_kernel(const float2* __restrict__ src, __half2* __restrict__ q,
                             float* __restrict__ sc, int ngroups){
  int w=(blockIdx.x*blockDim.x+threadIdx.x)>>5, lane=threadIdx.x&31, nw=(gridDim.x*blockDim.x)>>5;
  for (int g=w; g<ngroups; g+=nw){
    float2 v = src[g*32+lane];
    float m = fmaxf(fabsf(v.x),fabsf(v.y));
#pragma unroll
    for (int o=16;o;o>>=1) m=fmaxf(m,__shfl_xor_sync(0xffffffffu,m,o));
    float s=fmaxf(m,1e-5f), inv=127.0f/s;
    float q0=(float)__float2int_rn(v.x*inv);
    float q1=(float)__float2int_rn(v.y*inv);
    q[g*32+lane]=__floats2half2_rn(q0,q1);
    if (lane==0) sc[g]=s*(1.0f/127.0f);
  }
}

// ---------------- grouped fp16 GEMM with bit-packed B, 512 thr / 16 warps ----
// CTA tile 128x128, warp grid 4x4, warp tile 32x32 (MT=2 m16, NT=4 n8), K-chunk 64.
// A = q (fp16-exact ints) via ldmatrix; B = ±1 synthesized from bits (no ldsm).
// MODE 0: dual-B (w1,w2); epilogue SwiGLU + fused 64-col-group quant -> g_hqh,g_sh
// MODE 1: single-B (w3); epilogue scale -> C
#define ATILE 16384    // 128 rows x 128 B (64 halves)

template<int NB, int KTOT>
__device__ __forceinline__ void load_stage_d(uint32_t st, const __half* A, const float* sA,
    const uint32_t* B1b, const uint32_t* B2b, int m0, int nb0, int g, int tid)
{
#pragma unroll
  for (int t=0;t<2;t++){
    int i = tid + t*512, r = i>>3, c = i&7;
    cpa16(st + r*128 + ((c ^ (r&7))<<4), A + (size_t)(m0+r)*KTOT + g*64 + c*8);
  }
  if (tid >= 128 && tid < 128 + 64*NB){
    int u = tid-128, b = u>>6; u &= 63;
    const uint32_t* Bp = b ? B2b : B1b;
    cpa16(st + ATILE + b*1024 + (u>>2)*64 + (u&3)*16,
          Bp + ((size_t)(nb0 + (u>>2))*(KTOT/64) + g)*16 + (u&3)*4);
  }
  if (tid < 128) cpa4(st + ATILE + NB*1024 + tid*4, sA + (size_t)(m0+tid)*(KTOT/64) + g);
  asm volatile("cp.async.commit_group;");
}

template<int MODE, int KTOT>
__global__ void __launch_bounds__(512,1) gemm_f16(
    const __half* __restrict__ A, const float* __restrict__ sA,
    const uint32_t* __restrict__ B1b, const uint32_t* __restrict__ B2b,
    float* __restrict__ C)
{
  constexpr int NB    = (MODE==0) ? 2 : 1;
  constexpr int NG    = KTOT/64;
  constexpr int STAGE = ATILE + NB*1024 + 512;
  extern __shared__ char smem[];
  const uint32_t sb = (uint32_t)__cvta_generic_to_shared(smem);
  const int tid = threadIdx.x, lane = tid&31, wid = tid>>5;
  const int m0 = blockIdx.y*128, n0 = blockIdx.x*128, nb0 = blockIdx.x*16;
  const int wm = (wid>>2)*32, wn = (wid&3)*32;

  const int arow = lane&15;          // A row within m16
  const int acs  = lane>>4;          // A 16B-chunk select (k half)
  const int bsh  = (lane&7)*4;       // bit-nibble shift for this lane
  const uint32_t boff = (uint32_t)((wid&3)*4)*64 + ((lane>>3)<<4);  // warp's ntile base in bits block

  float f1[2][4][4]; float f2[2][4][4];
#pragma unroll
  for (int i=0;i<2;i++)
#pragma unroll
    for (int j=0;j<4;j++)
#pragma unroll
      for (int k=0;k<4;k++){ f1[i][j][k]=0.f; if (MODE==0) f2[i][j][k]=0.f; }

  load_stage_d<NB,KTOT>(sb, A, sA, B1b, B2b, m0, nb0, 0, tid);

#pragma unroll 1
  for (int g=0; g<NG; ++g){
    const int s = g&1;
    if (g+1 < NG){
      load_stage_d<NB,KTOT>(sb + (s^1)*STAGE, A, sA, B1b, B2b, m0, nb0, g+1, tid);
      asm volatile("cp.async.wait_group 1;");
    } else {
      asm volatile("cp.async.wait_group 0;");
    }
    __syncthreads();

    const uint32_t st = sb + s*STAGE;
    const float* sf = (const float*)(smem + s*STAGE + ATILE + NB*1024);
    float sc[2][2];
#pragma unroll
    for (int mt=0;mt<2;mt++){
      sc[mt][0] = sf[wm + mt*16 + (lane>>2)];
      sc[mt][1] = sf[wm + mt*16 + (lane>>2) + 8];
    }

#pragma unroll
    for (int pass=0; pass<NB; ++pass){
      const uint32_t bbase = st + ATILE + (uint32_t)pass*1024 + boff;
      float dt[2][4][4];
#pragma unroll
      for (int i=0;i<2;i++)
#pragma unroll
        for (int j=0;j<4;j++)
#pragma unroll
          for (int k=0;k<4;k++) dt[i][j][k]=0.f;
#pragma unroll
      for (int ks=0;ks<4;ks++){
        uint32_t a[2][4];
#pragma unroll
        for (int mt=0;mt<2;mt++){
          int row = wm + mt*16 + arow, c = ks*2 + acs;
          ldsm4(a[mt], st + row*128 + ((c ^ (row&7))<<4));
        }
#pragma unroll
        for (int nt=0;nt<4;nt++){
          uint32_t wbits = lds32(bbase + (uint32_t)nt*64 + (uint32_t)ks*4);
          uint32_t nib = wbits >> bsh;
          uint32_t b[2];
          b[0] = 0x3C003C00u ^ ((nib&1u)<<15) ^ ((nib&2u)<<30);
          b[1] = 0x3C003C00u ^ ((nib&4u)<<13) ^ ((nib&8u)<<28);
#pragma unroll
          for (int mt=0;mt<2;mt++) hmma(dt[mt][nt], a[mt], b);
        }
      }
      if (pass==0){
#pragma unroll
        for (int mt=0;mt<2;mt++)
#pragma unroll
          for (int nt=0;nt<4;nt++){
            f1[mt][nt][0] += sc[mt][0]*dt[mt][nt][0];
            f1[mt][nt][1] += sc[mt][0]*dt[mt][nt][1];
            f1[mt][nt][2] += sc[mt][1]*dt[mt][nt][2];
            f1[mt][nt][3] += sc[mt][1]*dt[mt][nt][3];
          }
      } else {
#pragma unroll
        for (int mt=0;mt<2;mt++)
#pragma unroll
          for (int nt=0;nt<4;nt++){
            f2[mt][nt][0] += sc[mt][0]*dt[mt][nt][0];
            f2[mt][nt][1] += sc[mt][0]*dt[mt][nt][1];
            f2[mt][nt][2] += sc[mt][1]*dt[mt][nt][2];
            f2[mt][nt][3] += sc[mt][1]*dt[mt][nt][3];
          }
      }
    }
    __syncthreads();
  }

  // ---------------- epilogue ----------------
  if (MODE==0){
    float* smax = (float*)smem;                  // [grp(2)][half(2)][row(128)]
    const float c1=g_wscale[0], c2=g_wscale[1];
    const int grp = wn>>6, halfw=(wn>>5)&1;
    float rmax[2][2];
#pragma unroll
    for (int mt=0;mt<2;mt++)
#pragma unroll
      for (int hr=0;hr<2;hr++){
        float m=0.f;
#pragma unroll
        for (int nt=0;nt<4;nt++)
#pragma unroll
          for (int e=0;e<2;e++){
            float u=c1*f1[mt][nt][hr*2+e];
            float v=c2*f2[mt][nt][hr*2+e];
            float h=(u/(1.f+expf(-u)))*v;
            f1[mt][nt][hr*2+e]=h;
            m=fmaxf(m,fabsf(h));
          }
        m=fmaxf(m,__shfl_xor_sync(0xffffffffu,m,1));
        m=fmaxf(m,__shfl_xor_sync(0xffffffffu,m,2));
        rmax[mt][hr]=m;
      }
    if ((lane&3)==0){
#pragma unroll
      for (int mt=0;mt<2;mt++)
#pragma unroll
        for (int hr=0;hr<2;hr++){
          int rr=wm+mt*16+(lane>>2)+hr*8;
          smax[(grp*2+halfw)*128+rr]=rmax[mt][hr];
        }
    }
    __syncthreads();
#pragma unroll
    for (int mt=0;mt<2;mt++)
#pragma unroll
      for (int hr=0;hr<2;hr++){
        int rr=wm+mt*16+(lane>>2)+hr*8;
        int row=m0+rr;
        float m=fmaxf(rmax[mt][hr], smax[(grp*2+(halfw^1))*128+rr]);
        float s=fmaxf(m,1e-5f), inv=127.0f/s;
#pragma unroll
        for (int nt=0;nt<4;nt++){
          float q0=(float)__float2int_rn(f1[mt][nt][hr*2+0]*inv);
          float q1=(float)__float2int_rn(f1[mt][nt][hr*2+1]*inv);
          *(__half2*)&g_hqh[(size_t)row*DFF + n0+wn+nt*8+(lane&3)*2] = __floats2half2_rn(q0,q1);
        }
        if (halfw==0 && (lane&3)==0)
          g_sh[(size_t)row*NGH + (n0>>6)+grp]=s*(1.0f/127.0f);
      }
  } else {
    const float c3=g_wscale[2];
#pragma unroll
    for (int mt=0;mt<2;mt++)
#pragma unroll
      for (int nt=0;nt<4;nt++)
#pragma unroll
        for (int hr=0;hr<2;hr++){
          int row  = m0 + wm + mt*16 + (lane>>2) + hr*8;
          int cidx = n0 + wn + nt*8 + (lane&3)*2;
          *(float2*)&C[(size_t)row*DMODEL + cidx] =
              make_float2(c3*f1[mt][nt][hr*2+0], c3*f1[mt][nt][hr*2+1]);
        }
  }
}

// ---------------- host launcher ---------------------------------------------
extern "C" void kernel_launch(void* const* d_in, const int* in_sizes, int n_in,
                              void* d_out, int out_size)
{
  const float* x  = (const float*)d_in[0];
  const float* w1 = (const float*)d_in[1];
  const float* w2 = (const float*)d_in[2];
  const float* w3 = (const float*)d_in[3];

  void *w1b,*w2b,*w3b,*xq,*sx,*hq,*sh;
  cudaGetSymbolAddress(&w1b,g_w1b); cudaGetSymbolAddress(&w2b,g_w2b);
  cudaGetSymbolAddress(&w3b,g_w3b); cudaGetSymbolAddress(&xq ,g_xqh);
  cudaGetSymbolAddress(&sx ,g_sx ); cudaGetSymbolAddress(&hq ,g_hqh);
  cudaGetSymbolAddress(&sh ,g_sh );

  const int NW = DFF*DMODEL;       // 16.7M, same count for all three weights
  constexpr int SM0 = 2*(ATILE + 2*1024 + 512);   // 37888 B
  constexpr int SM1 = 2*(ATILE + 1*1024 + 512);   // 35840 B
  cudaFuncSetAttribute(gemm_f16<0,DMODEL>, cudaFuncAttributeMaxDynamicSharedMemorySize, SM0);
  cudaFuncSetAttribute(gemm_f16<1,DFF>,    cudaFuncAttributeMaxDynamicSharedMemorySize, SM1);

  // L1: pack sign bits + abs-sum partials (all three weights)
  prep_pack<<<dim3(2048,3),256>>>(w1, w2, w3,
                                  (uint32_t*)w1b, (uint32_t*)w2b, (uint32_t*)w3b);
  // L2: quantize x (store exact integer q as fp16)
  quant_kernel<<<2048,256>>>((const float2*)x, (__half2*)xq, (float*)sx, MTOK*NGX);
  // L3: finalize weight scales
  absmean_final3<<<3,256>>>(1.0f/(float)NW);
  // L4: fused GEMM1+2 + SwiGLU + h-quant -> g_hqh/g_sh
  gemm_f16<0,DMODEL><<<dim3(DFF/128, MTOK/128), 512, SM0>>>(
      (const __half*)xq, (const float*)sx,
      (const uint32_t*)w1b, (const uint32_t*)w2b, nullptr);
  // L5: GEMM3 -> out
  gemm_f16<1,DFF><<<dim3(DMODEL/128, MTOK/128), 512, SM1>>>(
      (const __half*)hq, (const float*)sh,
      (const uint32_t*)w3b, nullptr, (float*)d_out);
}